// round 2
// baseline (speedup 1.0000x reference)
#include <cuda_runtime.h>
#include <cstdint>

// ---------------- problem constants ----------------
#define NE 8192
#define NI 2048
#define NN (NE + NI)   // 10240
#define BB 16
#define TT 100
#define CAP 768        // per-column per-class capacity (mean 512, sigma ~22 -> 12 sigma)

// exp/dt constants, double literals rounded to float to match float(np.exp(...))
#define EXP_SYN_F  ((float)0.6065306597126334)   // exp(-0.5)
#define DT_SYN_F   0.5f
#define EXP_NMDA_F ((float)0.9512294245007140)   // exp(-0.05)
#define DT_NMDA_F  0.05f
#define EXP_TAU_F  ((float)0.6065306597126334)   // exp(-0.5)
#define DT_TAU_F   0.5f
#define R_NMDA_F   0.4f

// ---------------- device scratch (no allocations allowed) ----------------
__device__ float g_rates[2][NN * BB];   // ping-pong rates, layout [n][b]
__device__ float g_rec0[NN * BB];
__device__ float g_rec1[NN * BB];
__device__ float g_u[NE * BB];
__device__ float g_x[NE * BB];
__device__ float g_aux[NE * BB];

__device__ int g_cntE[NN];
__device__ int g_cntI[NN];
__device__ int g_cntS[NE];

// pair = (index as int bits, weight value)
__device__ float2 g_pairE[(size_t)NN * CAP];
__device__ float2 g_pairI[(size_t)NN * CAP];
__device__ float2 g_pairS[(size_t)NE * CAP];

// ---------------- preprocessing ----------------
__global__ void k_zero_counts() {
    int i = blockIdx.x * blockDim.x + threadIdx.x;
    if (i < NN) { g_cntE[i] = 0; g_cntI[i] = 0; }
    if (i < NE) { g_cntS[i] = 0; }
}

__global__ void k_fill_wab(const float* __restrict__ W) {
    long long idx = (long long)blockIdx.x * blockDim.x + threadIdx.x;
    if (idx >= (long long)NN * NN) return;
    float w = W[idx];
    if (w != 0.0f) {
        int m = (int)(idx / NN);
        int n = (int)(idx - (long long)m * NN);
        if (m < NE) {
            int p = atomicAdd(&g_cntE[n], 1);
            if (p < CAP) g_pairE[(size_t)n * CAP + p] = make_float2(__int_as_float(m), w);
        } else {
            int p = atomicAdd(&g_cntI[n], 1);
            if (p < CAP) g_pairI[(size_t)n * CAP + p] = make_float2(__int_as_float(m), w);
        }
    }
}

__global__ void k_fill_wstp(const float* __restrict__ W) {
    long long idx = (long long)blockIdx.x * blockDim.x + threadIdx.x;
    if (idx >= (long long)NE * NE) return;
    float w = W[idx];
    if (w != 0.0f) {
        int m = (int)(idx / NE);
        int n = (int)(idx - (long long)m * NE);
        int p = atomicAdd(&g_cntS[n], 1);
        if (p < CAP) g_pairS[(size_t)n * CAP + p] = make_float2(__int_as_float(m), w);
    }
}

// ---------------- state init ----------------
__global__ void k_init(const float* __restrict__ ff, const float* __restrict__ rec) {
    int gid = blockIdx.x * blockDim.x + threadIdx.x;
    if (gid >= NN * BB) return;
    int n = gid >> 4;
    int b = gid & 15;
    float r0 = rec[(size_t)b * NN + n];            // rec_input[0][b][n]
    float r1 = rec[(size_t)(BB + b) * NN + n];     // rec_input[1][b][n]
    g_rec0[gid] = r0;
    g_rec1[gid] = r1;
    float f = ff[((size_t)b * TT + 0) * NN + n];
    float v = f + r0 - 1.0f;
    g_rates[0][gid] = v > 0.0f ? v : 0.0f;
    if (n < NE) {   // for n < NE, gid == n*16+b indexes [m][b] of E block
        g_u[gid] = 0.03f;
        g_x[gid] = 1.0f;
    }
}

// ---------------- per-step STP elementwise update ----------------
__global__ void k_stp(int par) {
    int gid = blockIdx.x * blockDim.x + threadIdx.x;
    if (gid >= NE * BB) return;
    const float* rcur = g_rates[par];
    float re = rcur[gid];           // E neurons are the first NE rows
    float u = g_u[gid];
    float x = g_x[gid];
    // u = u + DT*(USE-u)/TAU_FAC + USE*(1-u)*re*DT    (old u on RHS)
    u = u + 0.01f * (0.03f - u) + 0.03f * (1.0f - u) * re * 0.01f;
    // x = x + DT*(1-x)/TAU_REC - u_new*x_old*re*DT
    x = x + 0.04f * (1.0f - x) - u * x * re * 0.01f;
    g_u[gid] = u;
    g_x[gid] = x;
    g_aux[gid] = u * x * re;
}

// ---------------- main step kernel: one warp per output neuron ----------------
__global__ void __launch_bounds__(256) k_step(const float* __restrict__ ff,
                                              float* __restrict__ out,
                                              int t, int par) {
    int warp = (blockIdx.x * blockDim.x + threadIdx.x) >> 5;
    if (warp >= NN) return;
    const int n    = warp;
    const int lane = threadIdx.x & 31;
    const int b    = lane & 15;
    const int j    = lane >> 4;      // half-warp selects odd/even nnz

    const float* __restrict__ rcur  = g_rates[par];
    float*       __restrict__ rnext = g_rates[par ^ 1];

    float accE = 0.0f, accI = 0.0f, accS = 0.0f;

    // E-presyn part of Wab_T column n (zero for n < NE by construction)
    {
        int c = min(g_cntE[n], CAP);
        const float2* __restrict__ p = &g_pairE[(size_t)n * CAP];
        #pragma unroll 4
        for (int k = j; k < c; k += 2) {
            float2 pr = __ldg(&p[k]);
            int m = __float_as_int(pr.x);
            accE += pr.y * __ldg(&rcur[m * BB + b]);
        }
    }
    // I-presyn part of Wab_T column n
    {
        int c = min(g_cntI[n], CAP);
        const float2* __restrict__ p = &g_pairI[(size_t)n * CAP];
        #pragma unroll 4
        for (int k = j; k < c; k += 2) {
            float2 pr = __ldg(&p[k]);
            int m = __float_as_int(pr.x);
            accI += pr.y * __ldg(&rcur[m * BB + b]);
        }
    }
    // STP part (only E outputs)
    if (n < NE) {
        int c = min(g_cntS[n], CAP);
        const float2* __restrict__ p = &g_pairS[(size_t)n * CAP];
        #pragma unroll 4
        for (int k = j; k < c; k += 2) {
            float2 pr = __ldg(&p[k]);
            int m = __float_as_int(pr.x);
            accS += pr.y * __ldg(&g_aux[m * BB + b]);
        }
    }

    // combine the two half-warp partial sums (lanes l and l^16 share batch b)
    accE += __shfl_xor_sync(0xffffffffu, accE, 16);
    accI += __shfl_xor_sync(0xffffffffu, accI, 16);
    accS += __shfl_xor_sync(0xffffffffu, accS, 16);

    if (j == 0) {
        int e = n * BB + b;
        float hidden  = accE + accI + accS;   // rates@Wab_T (+ h_stp on E cols)
        float hidden2 = accE + accS;          // re@Wab_E    (+ h_stp on E cols)

        float rec0 = g_rec0[e] * EXP_SYN_F  + hidden  * DT_SYN_F;
        float rec1 = g_rec1[e] * EXP_NMDA_F + R_NMDA_F * hidden2 * DT_NMDA_F;
        g_rec0[e] = rec0;
        g_rec1[e] = rec1;

        float net = ff[((size_t)b * TT + t) * NN + n] + rec0 + rec1;
        float nl  = net - 1.0f;
        nl = nl > 0.0f ? nl : 0.0f;
        float rn = rcur[e] * EXP_TAU_F + nl * DT_TAU_F;
        rnext[e] = rn;
        out[((size_t)b * TT + t) * NN + n] = rn;
    }
}

// ---------------- launcher ----------------
extern "C" void kernel_launch(void* const* d_in, const int* in_sizes, int n_in,
                              void* d_out, int out_size) {
    // Identify inputs robustly by element count.
    const float* ff   = nullptr;   // 16*100*10240 = 16384000
    const float* rec  = nullptr;   // 2*16*10240   = 327680
    const float* wab  = nullptr;   // 10240*10240  = 104857600
    const float* wstp = nullptr;   // 8192*8192    = 67108864
    for (int i = 0; i < n_in; ++i) {
        switch (in_sizes[i]) {
            case 16384000:  ff   = (const float*)d_in[i]; break;
            case 327680:    rec  = (const float*)d_in[i]; break;
            case 104857600: wab  = (const float*)d_in[i]; break;
            case 67108864:  wstp = (const float*)d_in[i]; break;
            default: break;
        }
    }
    if (!ff || !rec || !wab || !wstp) {
        // fall back to declared order
        ff   = (const float*)d_in[0];
        rec  = (const float*)d_in[1];
        wab  = (const float*)d_in[2];
        wstp = (const float*)d_in[3];
    }
    float* out = (float*)d_out;

    // 1) rebuild sparse lists (required every call; no caching allowed)
    k_zero_counts<<<(NN + 255) / 256, 256>>>();
    {
        long long tot = (long long)NN * NN;
        k_fill_wab<<<(unsigned)((tot + 255) / 256), 256>>>(wab);
    }
    {
        long long tot = (long long)NE * NE;
        k_fill_wstp<<<(unsigned)((tot + 255) / 256), 256>>>(wstp);
    }

    // 2) init state
    k_init<<<(NN * BB + 255) / 256, 256>>>(ff, rec);

    // 3) time loop: 100 steps, 2 kernels each
    const int step_blocks = (NN * 32 + 255) / 256;   // one warp per neuron
    for (int t = 0; t < TT; ++t) {
        int par = t & 1;
        k_stp<<<(NE * BB + 255) / 256, 256>>>(par);
        k_step<<<step_blocks, 256>>>(ff, out, t, par);
    }
}

// round 3
// speedup vs baseline: 1.7926x; 1.7926x over previous
#include <cuda_runtime.h>
#include <cuda_fp16.h>
#include <cstdint>

// ---------------- problem constants ----------------
#define NE 8192
#define NI 2048
#define NN (NE + NI)   // 10240
#define BB 16
#define TT 100
#define CAP 768        // per-column per-class capacity (mean 512, sigma ~22)

#define EXP_SYN_F  ((float)0.6065306597126334)   // exp(-0.5)
#define DT_SYN_F   0.5f
#define EXP_NMDA_F ((float)0.9512294245007140)   // exp(-0.05)
#define DT_NMDA_F  0.05f
#define EXP_TAU_F  ((float)0.6065306597126334)   // exp(-0.5)
#define DT_TAU_F   0.5f
#define R_NMDA_F   0.4f

// ---------------- device scratch ----------------
__device__ float  g_ratesf[NN * BB];      // fp32 rate state, in-place per (n,b)
__device__ __half g_r16[2][NN * BB];      // fp16 gather copy, ping-pong
__device__ __half g_aux16[2][NE * BB];    // fp16 STP aux, ping-pong
__device__ float  g_rec0[NN * BB];
__device__ float  g_rec1[NN * BB];
__device__ float  g_u[NE * BB];
__device__ float  g_x[NE * BB];

__device__ int g_cntE[NN];
__device__ int g_cntI[NN];
__device__ int g_cntS[NE];

// index-only connectivity (all weights within a class are equal)
__device__ unsigned short g_idxE[(size_t)NN * CAP];  // m in [0,NE)
__device__ unsigned short g_idxI[(size_t)NN * CAP];  // m-NE in [0,NI)
__device__ unsigned short g_idxS[(size_t)NE * CAP];  // m in [0,NE)
__device__ float g_sclE[NN];
__device__ float g_sclI[NN];
__device__ float g_sclS[NE];

// ---------------- preprocessing ----------------
__global__ void k_zero() {
    int i = blockIdx.x * blockDim.x + threadIdx.x;
    if (i < NN) { g_cntE[i] = 0; g_cntI[i] = 0; g_sclE[i] = 0.0f; g_sclI[i] = 0.0f; }
    if (i < NE) { g_cntS[i] = 0; g_sclS[i] = 0.0f; }
}

__global__ void k_fill_wab(const float* __restrict__ W) {
    long long idx = (long long)blockIdx.x * blockDim.x + threadIdx.x;
    if (idx >= (long long)NN * NN) return;
    float w = W[idx];
    if (w != 0.0f) {
        int m = (int)(idx / NN);
        int n = (int)(idx - (long long)m * NN);
        if (m < NE) {
            int p = atomicAdd(&g_cntE[n], 1);
            if (p < CAP) {
                g_idxE[(size_t)n * CAP + p] = (unsigned short)m;
                if (p == 0) g_sclE[n] = w;
            }
        } else {
            int p = atomicAdd(&g_cntI[n], 1);
            if (p < CAP) {
                g_idxI[(size_t)n * CAP + p] = (unsigned short)(m - NE);
                if (p == 0) g_sclI[n] = w;
            }
        }
    }
}

__global__ void k_fill_wstp(const float* __restrict__ W) {
    long long idx = (long long)blockIdx.x * blockDim.x + threadIdx.x;
    if (idx >= (long long)NE * NE) return;
    float w = W[idx];
    if (w != 0.0f) {
        int m = (int)(idx / NE);
        int n = (int)(idx - (long long)m * NE);
        int p = atomicAdd(&g_cntS[n], 1);
        if (p < CAP) {
            g_idxS[(size_t)n * CAP + p] = (unsigned short)m;
            if (p == 0) g_sclS[n] = w;
        }
    }
}

// ---------------- state init (also computes step-0 STP aux) ----------------
__global__ void k_init(const float* __restrict__ ff, const float* __restrict__ rec) {
    int gid = blockIdx.x * blockDim.x + threadIdx.x;
    if (gid >= NN * BB) return;
    int n = gid >> 4;
    int b = gid & 15;
    float r0 = rec[(size_t)b * NN + n];
    float r1 = rec[(size_t)(BB + b) * NN + n];
    g_rec0[gid] = r0;
    g_rec1[gid] = r1;
    float f = ff[((size_t)b * TT + 0) * NN + n];
    float v = f + r0 - 1.0f;
    v = v > 0.0f ? v : 0.0f;
    g_ratesf[gid]  = v;
    g_r16[0][gid]  = __float2half_rn(v);
    if (n < NE) {
        // step-0 STP update with u0=USE, x0=1, re = v
        float u = 0.03f;
        float x = 1.0f;
        u = u + 0.01f * (0.03f - u) + 0.03f * (1.0f - u) * v * 0.01f;
        x = x + 0.04f * (1.0f - x) - u * x * v * 0.01f;
        g_u[gid] = u;
        g_x[gid] = x;
        g_aux16[0][gid] = __float2half_rn(u * x * v);
    }
}

// ---------------- fused step kernel: one warp per output neuron ----------------
__global__ void __launch_bounds__(256) k_step(const float* __restrict__ ff,
                                              float* __restrict__ out,
                                              int t, int par) {
    int warp = (blockIdx.x * blockDim.x + threadIdx.x) >> 5;
    if (warp >= NN) return;
    const int n    = warp;
    const int lane = threadIdx.x & 31;
    const int b    = lane & 15;
    const int j    = lane >> 4;     // half-warp: even/odd index packs

    const __half* __restrict__ rE = &g_r16[par][0];            // E rates
    const __half* __restrict__ rI = &g_r16[par][NE * BB];      // I rates
    const __half* __restrict__ aS = &g_aux16[par][0];          // STP aux

    float accE = 0.0f, accI = 0.0f, accS = 0.0f;

    // E-presyn sum (empty for n < NE)
    {
        int c = min(g_cntE[n], CAP);
        const unsigned int* __restrict__ p32 =
            (const unsigned int*)&g_idxE[(size_t)n * CAP];
        int npk = c >> 1;
        #pragma unroll 4
        for (int pk = j; pk < npk; pk += 2) {
            unsigned int pack = __ldg(&p32[pk]);
            int m0 = (int)(pack & 0xffffu);
            int m1 = (int)(pack >> 16);
            accE += __half2float(__ldg(&rE[m0 * BB + b]));
            accE += __half2float(__ldg(&rE[m1 * BB + b]));
        }
        if ((c & 1) && j == 0)
            accE += __half2float(__ldg(&rE[(int)g_idxE[(size_t)n * CAP + c - 1] * BB + b]));
    }
    // I-presyn sum
    {
        int c = min(g_cntI[n], CAP);
        const unsigned int* __restrict__ p32 =
            (const unsigned int*)&g_idxI[(size_t)n * CAP];
        int npk = c >> 1;
        #pragma unroll 4
        for (int pk = j; pk < npk; pk += 2) {
            unsigned int pack = __ldg(&p32[pk]);
            int m0 = (int)(pack & 0xffffu);
            int m1 = (int)(pack >> 16);
            accI += __half2float(__ldg(&rI[m0 * BB + b]));
            accI += __half2float(__ldg(&rI[m1 * BB + b]));
        }
        if ((c & 1) && j == 0)
            accI += __half2float(__ldg(&rI[(int)g_idxI[(size_t)n * CAP + c - 1] * BB + b]));
    }
    // STP sum (E outputs only)
    if (n < NE) {
        int c = min(g_cntS[n], CAP);
        const unsigned int* __restrict__ p32 =
            (const unsigned int*)&g_idxS[(size_t)n * CAP];
        int npk = c >> 1;
        #pragma unroll 4
        for (int pk = j; pk < npk; pk += 2) {
            unsigned int pack = __ldg(&p32[pk]);
            int m0 = (int)(pack & 0xffffu);
            int m1 = (int)(pack >> 16);
            accS += __half2float(__ldg(&aS[m0 * BB + b]));
            accS += __half2float(__ldg(&aS[m1 * BB + b]));
        }
        if ((c & 1) && j == 0)
            accS += __half2float(__ldg(&aS[(int)g_idxS[(size_t)n * CAP + c - 1] * BB + b]));
    }

    // combine half-warp partials (lane l and l^16 share batch b)
    accE += __shfl_xor_sync(0xffffffffu, accE, 16);
    accI += __shfl_xor_sync(0xffffffffu, accI, 16);
    accS += __shfl_xor_sync(0xffffffffu, accS, 16);

    if (j == 0) {
        int e = n * BB + b;
        float sE = g_sclE[n] * accE;
        float sI = g_sclI[n] * accI;
        float sS = (n < NE) ? g_sclS[n] * accS : 0.0f;

        float hidden  = sE + sI + sS;   // rates@Wab_T (+h_stp)
        float hidden2 = sE + sS;        // re@Wab_E    (+h_stp)

        float rec0 = g_rec0[e] * EXP_SYN_F  + hidden  * DT_SYN_F;
        float rec1 = g_rec1[e] * EXP_NMDA_F + R_NMDA_F * hidden2 * DT_NMDA_F;
        g_rec0[e] = rec0;
        g_rec1[e] = rec1;

        float net = ff[((size_t)b * TT + t) * NN + n] + rec0 + rec1;
        float nl  = net - 1.0f;
        nl = nl > 0.0f ? nl : 0.0f;
        float rn = g_ratesf[e] * EXP_TAU_F + nl * DT_TAU_F;
        g_ratesf[e] = rn;
        g_r16[par ^ 1][e] = __float2half_rn(rn);
        out[((size_t)b * TT + t) * NN + n] = rn;

        // fused STP update producing aux for the NEXT step (re = rn)
        if (n < NE) {
            float u = g_u[e];
            float x = g_x[e];
            u = u + 0.01f * (0.03f - u) + 0.03f * (1.0f - u) * rn * 0.01f;
            x = x + 0.04f * (1.0f - x) - u * x * rn * 0.01f;
            g_u[e] = u;
            g_x[e] = x;
            g_aux16[par ^ 1][e] = __float2half_rn(u * x * rn);
        }
    }
}

// ---------------- launcher ----------------
extern "C" void kernel_launch(void* const* d_in, const int* in_sizes, int n_in,
                              void* d_out, int out_size) {
    const float* ff   = nullptr;   // 16*100*10240
    const float* rec  = nullptr;   // 2*16*10240
    const float* wab  = nullptr;   // 10240*10240
    const float* wstp = nullptr;   // 8192*8192
    for (int i = 0; i < n_in; ++i) {
        switch (in_sizes[i]) {
            case 16384000:  ff   = (const float*)d_in[i]; break;
            case 327680:    rec  = (const float*)d_in[i]; break;
            case 104857600: wab  = (const float*)d_in[i]; break;
            case 67108864:  wstp = (const float*)d_in[i]; break;
            default: break;
        }
    }
    if (!ff || !rec || !wab || !wstp) {
        ff   = (const float*)d_in[0];
        rec  = (const float*)d_in[1];
        wab  = (const float*)d_in[2];
        wstp = (const float*)d_in[3];
    }
    float* out = (float*)d_out;

    // 1) rebuild index lists (every call; no caching allowed)
    k_zero<<<(NN + 255) / 256, 256>>>();
    {
        long long tot = (long long)NN * NN;
        k_fill_wab<<<(unsigned)((tot + 255) / 256), 256>>>(wab);
    }
    {
        long long tot = (long long)NE * NE;
        k_fill_wstp<<<(unsigned)((tot + 255) / 256), 256>>>(wstp);
    }

    // 2) init state (+ step-0 aux)
    k_init<<<(NN * BB + 255) / 256, 256>>>(ff, rec);

    // 3) 100 fused steps
    const int step_blocks = (NN * 32 + 255) / 256;
    for (int t = 0; t < TT; ++t) {
        k_step<<<step_blocks, 256>>>(ff, out, t, t & 1);
    }
}

// round 4
// speedup vs baseline: 2.4151x; 1.3473x over previous
#include <cuda_runtime.h>
#include <cuda_fp16.h>
#include <cstdint>

// ---------------- problem constants ----------------
#define NE 8192
#define NI 2048
#define NN (NE + NI)   // 10240
#define BB 16
#define TT 100
#define CAP 768        // per-column per-class capacity (mean 512, +11.7 sigma)

#define EXP_SYN_F  ((float)0.6065306597126334)   // exp(-0.5)
#define DT_SYN_F   0.5f
#define EXP_NMDA_F ((float)0.9512294245007140)   // exp(-0.05)
#define DT_NMDA_F  0.05f
#define EXP_TAU_F  ((float)0.6065306597126334)   // exp(-0.5)
#define DT_TAU_F   0.5f
#define R_NMDA_F   0.4f

// ---------------- device scratch ----------------
// class-split fp16 gather arrays, ping-pong; one sentinel (zero) row each
__device__ __align__(256) __half g_rE16[2][(NE + 1) * BB];
__device__ __align__(256) __half g_rI16[2][(NI + 1) * BB];
__device__ __align__(256) __half g_aux16[2][(NE + 1) * BB];

__device__ float g_ratesf[NN * BB];   // fp32 rate state (in-place)
__device__ float g_rec0[NN * BB];
__device__ float g_rec1[NN * BB];
__device__ float g_u[NE * BB];
__device__ float g_x[NE * BB];

__device__ int g_cntE[NN];
__device__ int g_cntI[NN];
__device__ int g_cntS[NE];

__device__ __align__(256) unsigned short g_idxE[(size_t)NN * CAP];  // m in [0,NE], NE = sentinel
__device__ __align__(256) unsigned short g_idxI[(size_t)NN * CAP];  // m-NE in [0,NI], NI = sentinel
__device__ __align__(256) unsigned short g_idxS[(size_t)NE * CAP];  // m in [0,NE], NE = sentinel
__device__ float g_sclE[NN];
__device__ float g_sclI[NN];
__device__ float g_sclS[NE];

// ---------------- preprocessing ----------------
__global__ void k_zero() {
    int i = blockIdx.x * blockDim.x + threadIdx.x;
    if (i < NN) { g_cntE[i] = 0; g_cntI[i] = 0; g_sclE[i] = 0.0f; g_sclI[i] = 0.0f; }
    if (i < NE) { g_cntS[i] = 0; g_sclS[i] = 0.0f; }
}

__global__ void k_fill_wab(const float* __restrict__ W) {
    long long idx = (long long)blockIdx.x * blockDim.x + threadIdx.x;
    if (idx >= (long long)NN * NN) return;
    float w = W[idx];
    if (w != 0.0f) {
        int m = (int)(idx / NN);
        int n = (int)(idx - (long long)m * NN);
        if (m < NE) {
            int p = atomicAdd(&g_cntE[n], 1);
            if (p < CAP) {
                g_idxE[(size_t)n * CAP + p] = (unsigned short)m;
                if (p == 0) g_sclE[n] = w;
            }
        } else {
            int p = atomicAdd(&g_cntI[n], 1);
            if (p < CAP) {
                g_idxI[(size_t)n * CAP + p] = (unsigned short)(m - NE);
                if (p == 0) g_sclI[n] = w;
            }
        }
    }
}

__global__ void k_fill_wstp(const float* __restrict__ W) {
    long long idx = (long long)blockIdx.x * blockDim.x + threadIdx.x;
    if (idx >= (long long)NE * NE) return;
    float w = W[idx];
    if (w != 0.0f) {
        int m = (int)(idx / NE);
        int n = (int)(idx - (long long)m * NE);
        int p = atomicAdd(&g_cntS[n], 1);
        if (p < CAP) {
            g_idxS[(size_t)n * CAP + p] = (unsigned short)m;
            if (p == 0) g_sclS[n] = w;
        }
    }
}

// pad each column's index list to a multiple of 64 with the sentinel index
__global__ void k_pad() {
    int n = blockIdx.x * blockDim.x + threadIdx.x;
    if (n < NN) {
        int c = min(g_cntE[n], CAP);
        int cp = (c + 63) & ~63;
        for (int k = c; k < cp; ++k) g_idxE[(size_t)n * CAP + k] = (unsigned short)NE;
        c = min(g_cntI[n], CAP);
        cp = (c + 63) & ~63;
        for (int k = c; k < cp; ++k) g_idxI[(size_t)n * CAP + k] = (unsigned short)NI;
    }
    if (n < NE) {
        int c = min(g_cntS[n], CAP);
        int cp = (c + 63) & ~63;
        for (int k = c; k < cp; ++k) g_idxS[(size_t)n * CAP + k] = (unsigned short)NE;
    }
}

// ---------------- state init ----------------
__global__ void k_init(const float* __restrict__ ff, const float* __restrict__ rec) {
    int gid = blockIdx.x * blockDim.x + threadIdx.x;
    if (gid < 16) {  // zero sentinel rows in both ping-pong copies
        g_rE16[0][NE * BB + gid] = __float2half_rn(0.0f);
        g_rE16[1][NE * BB + gid] = __float2half_rn(0.0f);
        g_rI16[0][NI * BB + gid] = __float2half_rn(0.0f);
        g_rI16[1][NI * BB + gid] = __float2half_rn(0.0f);
        g_aux16[0][NE * BB + gid] = __float2half_rn(0.0f);
        g_aux16[1][NE * BB + gid] = __float2half_rn(0.0f);
    }
    if (gid >= NN * BB) return;
    int n = gid >> 4;
    int b = gid & 15;
    float r0 = rec[(size_t)b * NN + n];
    float r1 = rec[(size_t)(BB + b) * NN + n];
    g_rec0[gid] = r0;
    g_rec1[gid] = r1;
    float f = ff[((size_t)b * TT + 0) * NN + n];
    float v = f + r0 - 1.0f;
    v = v > 0.0f ? v : 0.0f;
    g_ratesf[gid] = v;
    if (n < NE) {
        g_rE16[0][gid] = __float2half_rn(v);
        float u = 0.03f, x = 1.0f;
        u = u + 0.01f * (0.03f - u) + 0.03f * (1.0f - u) * v * 0.01f;
        x = x + 0.04f * (1.0f - x) - u * x * v * 0.01f;
        g_u[gid] = u;
        g_x[gid] = x;
        g_aux16[0][gid] = __float2half_rn(u * x * v);
    } else {
        g_rI16[0][(n - NE) * BB + b] = __float2half_rn(v);
    }
}

// -------- gather-sum helper: 16 nnz per warp-instruction, fp16 chunk acc --------
__device__ __forceinline__ void gather_class(
    const unsigned short* __restrict__ idx, int cpad,
    const char* __restrict__ rbase, int q, int h16,
    float2& f0, float2& f1, float2& f2, float2& f3)
{
    for (int it = 0; it < cpad; it += 64) {
        __half2 a0 = __float2half2_rn(0.0f);
        __half2 a1 = a0, a2 = a0, a3 = a0;
        #pragma unroll
        for (int s = 0; s < 4; ++s) {
            int m = (int)__ldg(&idx[it + s * 16 + q]);
            uint4 v = __ldg((const uint4*)(rbase + (size_t)m * 32 + h16));
            a0 = __hadd2(a0, *reinterpret_cast<__half2*>(&v.x));
            a1 = __hadd2(a1, *reinterpret_cast<__half2*>(&v.y));
            a2 = __hadd2(a2, *reinterpret_cast<__half2*>(&v.z));
            a3 = __hadd2(a3, *reinterpret_cast<__half2*>(&v.w));
        }
        float2 t;
        t = __half22float2(a0); f0.x += t.x; f0.y += t.y;
        t = __half22float2(a1); f1.x += t.x; f1.y += t.y;
        t = __half22float2(a2); f2.x += t.x; f2.y += t.y;
        t = __half22float2(a3); f3.x += t.x; f3.y += t.y;
    }
}

__device__ __forceinline__ void bfly_reduce(float2& v) {
    #pragma unroll
    for (int o = 2; o < 32; o <<= 1) {
        v.x += __shfl_xor_sync(0xffffffffu, v.x, o);
        v.y += __shfl_xor_sync(0xffffffffu, v.y, o);
    }
}

// ---------------- fused step kernel: one warp per output neuron ----------------
__global__ void __launch_bounds__(256) k_step(const float* __restrict__ ff,
                                              float* __restrict__ out,
                                              int t, int par) {
    int warp = (blockIdx.x * blockDim.x + threadIdx.x) >> 5;
    if (warp >= NN) return;
    const int n    = warp;
    const int lane = threadIdx.x & 31;
    const int q    = lane >> 1;        // nnz slot within group of 16
    const int h    = lane & 1;         // batch half: 0 -> b 0..7, 1 -> b 8..15
    const int h16  = h * 16;

    const char* __restrict__ rE = (const char*)&g_rE16[par][0];
    const char* __restrict__ rI = (const char*)&g_rI16[par][0];
    const char* __restrict__ aS = (const char*)&g_aux16[par][0];

    float2 z = make_float2(0.0f, 0.0f);
    float2 fE0 = z, fE1 = z, fE2 = z, fE3 = z;
    float2 fI0 = z, fI1 = z, fI2 = z, fI3 = z;
    float2 fS0 = z, fS1 = z, fS2 = z, fS3 = z;

    {   // E-presyn (empty for n < NE by construction)
        int c = min(g_cntE[n], CAP);
        int cpad = (c + 63) & ~63;
        gather_class(&g_idxE[(size_t)n * CAP], cpad, rE, q, h16, fE0, fE1, fE2, fE3);
    }
    {   // I-presyn
        int c = min(g_cntI[n], CAP);
        int cpad = (c + 63) & ~63;
        gather_class(&g_idxI[(size_t)n * CAP], cpad, rI, q, h16, fI0, fI1, fI2, fI3);
    }
    if (n < NE) {   // STP (E outputs only)
        int c = min(g_cntS[n], CAP);
        int cpad = (c + 63) & ~63;
        gather_class(&g_idxS[(size_t)n * CAP], cpad, aS, q, h16, fS0, fS1, fS2, fS3);
    }

    // butterfly over the 16 lanes sharing the same batch-half h
    bfly_reduce(fE0); bfly_reduce(fE1); bfly_reduce(fE2); bfly_reduce(fE3);
    bfly_reduce(fI0); bfly_reduce(fI1); bfly_reduce(fI2); bfly_reduce(fI3);
    bfly_reduce(fS0); bfly_reduce(fS1); bfly_reduce(fS2); bfly_reduce(fS3);

    // epilogue: lanes 0 (batches 0-7) and 1 (batches 8-15)
    if (lane < 2) {
        float sclE = g_sclE[n];
        float sclI = g_sclI[n];
        float sclS = (n < NE) ? g_sclS[n] : 0.0f;
        float2 fE[4] = {fE0, fE1, fE2, fE3};
        float2 fI[4] = {fI0, fI1, fI2, fI3};
        float2 fS[4] = {fS0, fS1, fS2, fS3};

        __half* __restrict__ rEn = &g_rE16[par ^ 1][0];
        __half* __restrict__ rIn = &g_rI16[par ^ 1][0];
        __half* __restrict__ aSn = &g_aux16[par ^ 1][0];

        #pragma unroll
        for (int i = 0; i < 4; ++i) {
            int b0 = h * 8 + 2 * i;
            int e  = n * BB + b0;

            float sEx = sclE * fE[i].x, sEy = sclE * fE[i].y;
            float sIx = sclI * fI[i].x, sIy = sclI * fI[i].y;
            float sSx = sclS * fS[i].x, sSy = sclS * fS[i].y;

            float hidx  = sEx + sIx + sSx;
            float hidy  = sEy + sIy + sSy;
            float hid2x = sEx + sSx;
            float hid2y = sEy + sSy;

            float2 r0v = *reinterpret_cast<float2*>(&g_rec0[e]);
            float2 r1v = *reinterpret_cast<float2*>(&g_rec1[e]);
            r0v.x = r0v.x * EXP_SYN_F  + hidx * DT_SYN_F;
            r0v.y = r0v.y * EXP_SYN_F  + hidy * DT_SYN_F;
            r1v.x = r1v.x * EXP_NMDA_F + R_NMDA_F * hid2x * DT_NMDA_F;
            r1v.y = r1v.y * EXP_NMDA_F + R_NMDA_F * hid2y * DT_NMDA_F;
            *reinterpret_cast<float2*>(&g_rec0[e]) = r0v;
            *reinterpret_cast<float2*>(&g_rec1[e]) = r1v;

            float ffx = ff[((size_t)b0 * TT + t) * NN + n];
            float ffy = ff[((size_t)(b0 + 1) * TT + t) * NN + n];
            float netx = ffx + r0v.x + r1v.x - 1.0f;
            float nety = ffy + r0v.y + r1v.y - 1.0f;
            netx = netx > 0.0f ? netx : 0.0f;
            nety = nety > 0.0f ? nety : 0.0f;

            float2 rv = *reinterpret_cast<float2*>(&g_ratesf[e]);
            rv.x = rv.x * EXP_TAU_F + netx * DT_TAU_F;
            rv.y = rv.y * EXP_TAU_F + nety * DT_TAU_F;
            *reinterpret_cast<float2*>(&g_ratesf[e]) = rv;

            out[((size_t)b0 * TT + t) * NN + n]       = rv.x;
            out[((size_t)(b0 + 1) * TT + t) * NN + n] = rv.y;

            __half2 rh = __floats2half2_rn(rv.x, rv.y);
            if (n < NE) {
                *reinterpret_cast<__half2*>(&rEn[e]) = rh;
                // fused STP update (re = new rate)
                float2 uv = *reinterpret_cast<float2*>(&g_u[e]);
                float2 xv = *reinterpret_cast<float2*>(&g_x[e]);
                uv.x = uv.x + 0.01f * (0.03f - uv.x) + 0.03f * (1.0f - uv.x) * rv.x * 0.01f;
                uv.y = uv.y + 0.01f * (0.03f - uv.y) + 0.03f * (1.0f - uv.y) * rv.y * 0.01f;
                xv.x = xv.x + 0.04f * (1.0f - xv.x) - uv.x * xv.x * rv.x * 0.01f;
                xv.y = xv.y + 0.04f * (1.0f - xv.y) - uv.y * xv.y * rv.y * 0.01f;
                *reinterpret_cast<float2*>(&g_u[e]) = uv;
                *reinterpret_cast<float2*>(&g_x[e]) = xv;
                *reinterpret_cast<__half2*>(&aSn[e]) =
                    __floats2half2_rn(uv.x * xv.x * rv.x, uv.y * xv.y * rv.y);
            } else {
                *reinterpret_cast<__half2*>(&rIn[(n - NE) * BB + b0]) = rh;
            }
        }
    }
}

// ---------------- launcher ----------------
extern "C" void kernel_launch(void* const* d_in, const int* in_sizes, int n_in,
                              void* d_out, int out_size) {
    const float* ff   = nullptr;
    const float* rec  = nullptr;
    const float* wab  = nullptr;
    const float* wstp = nullptr;
    for (int i = 0; i < n_in; ++i) {
        switch (in_sizes[i]) {
            case 16384000:  ff   = (const float*)d_in[i]; break;
            case 327680:    rec  = (const float*)d_in[i]; break;
            case 104857600: wab  = (const float*)d_in[i]; break;
            case 67108864:  wstp = (const float*)d_in[i]; break;
            default: break;
        }
    }
    if (!ff || !rec || !wab || !wstp) {
        ff   = (const float*)d_in[0];
        rec  = (const float*)d_in[1];
        wab  = (const float*)d_in[2];
        wstp = (const float*)d_in[3];
    }
    float* out = (float*)d_out;

    k_zero<<<(NN + 255) / 256, 256>>>();
    {
        long long tot = (long long)NN * NN;
        k_fill_wab<<<(unsigned)((tot + 255) / 256), 256>>>(wab);
    }
    {
        long long tot = (long long)NE * NE;
        k_fill_wstp<<<(unsigned)((tot + 255) / 256), 256>>>(wstp);
    }
    k_pad<<<(NN + 255) / 256, 256>>>();
    k_init<<<(NN * BB + 255) / 256, 256>>>(ff, rec);

    const int step_blocks = (NN * 32 + 255) / 256;
    for (int t = 0; t < TT; ++t) {
        k_step<<<step_blocks, 256>>>(ff, out, t, t & 1);
    }
}

// round 5
// speedup vs baseline: 2.5899x; 1.0724x over previous
#include <cuda_runtime.h>
#include <cuda_fp16.h>
#include <cstdint>

// ---------------- problem constants ----------------
#define NE 8192
#define NI 2048
#define NN (NE + NI)   // 10240
#define BB 16
#define TT 100
#define CAP 768
#define BLOCK 512

#define EXP_SYN_F  ((float)0.6065306597126334)   // exp(-0.5)
#define DT_SYN_F   0.5f
#define EXP_NMDA_F ((float)0.9512294245007140)   // exp(-0.05)
#define DT_NMDA_F  0.05f
#define EXP_TAU_F  ((float)0.6065306597126334)
#define DT_TAU_F   0.5f
#define R_NMDA_F   0.4f

// ---------------- device scratch ----------------
__device__ __align__(256) __half g_rE16[2][(NE + 1) * BB];   // E rates + sentinel row
__device__ __align__(256) __half g_rI16[2][(NI + 1) * BB];   // I rates + sentinel row
__device__ __align__(256) __half g_aux16[2][(NE + 1) * BB];  // STP aux + sentinel row

__device__ float g_ratesf[NN * BB];
__device__ float g_rec0[NN * BB];
__device__ float g_rec1[NN * BB];
__device__ float g_u[NE * BB];
__device__ float g_x[NE * BB];

// two-class connectivity: every neuron has class A and class B
//   n <  NE: A = I-presyn (rI),  B = STP (aux)
//   n >= NE: A = E-presyn (rE),  B = I-presyn (rI)
__device__ int g_cntA[NN];
__device__ int g_cntB[NN];
__device__ __align__(256) unsigned short g_idxA[(size_t)NN * CAP];
__device__ __align__(256) unsigned short g_idxB[(size_t)NN * CAP];
__device__ float g_sclA[NN];
__device__ float g_sclB[NN];

// persistent-kernel sync / work-stealing state
__device__ int g_ctr[TT];
__device__ int g_bar;
__device__ volatile int g_sense;

// ---------------- preprocessing ----------------
__global__ void k_zero() {
    int i = blockIdx.x * blockDim.x + threadIdx.x;
    if (i < NN) { g_cntA[i] = 0; g_cntB[i] = 0; g_sclA[i] = 0.0f; g_sclB[i] = 0.0f; }
    if (i < TT) g_ctr[i] = 0;
    if (i == 0) { g_bar = 0; g_sense = 0; }
}

__global__ void k_fill_wab(const float* __restrict__ W) {
    long long i4 = (long long)blockIdx.x * blockDim.x + threadIdx.x;
    if (i4 >= (long long)NN * NN / 4) return;
    int m  = (int)(i4 / (NN / 4));
    int nb = (int)(i4 % (NN / 4)) * 4;
    float4 v = __ldg((const float4*)(W + (size_t)m * NN + nb));
    float wv[4] = {v.x, v.y, v.z, v.w};
    #pragma unroll
    for (int k = 0; k < 4; ++k) {
        float w = wv[k];
        if (w != 0.0f) {
            int n = nb + k;
            if (m < NE) {                 // E presyn -> class A of n (only n>=NE nonzero)
                int p = atomicAdd(&g_cntA[n], 1);
                if (p < CAP) {
                    g_idxA[(size_t)n * CAP + p] = (unsigned short)m;
                    if (p == 0) g_sclA[n] = w;
                }
            } else if (n < NE) {          // I presyn -> class A of E-output n
                int p = atomicAdd(&g_cntA[n], 1);
                if (p < CAP) {
                    g_idxA[(size_t)n * CAP + p] = (unsigned short)(m - NE);
                    if (p == 0) g_sclA[n] = w;
                }
            } else {                      // I presyn -> class B of I-output n
                int p = atomicAdd(&g_cntB[n], 1);
                if (p < CAP) {
                    g_idxB[(size_t)n * CAP + p] = (unsigned short)(m - NE);
                    if (p == 0) g_sclB[n] = w;
                }
            }
        }
    }
}

__global__ void k_fill_wstp(const float* __restrict__ W) {
    long long i4 = (long long)blockIdx.x * blockDim.x + threadIdx.x;
    if (i4 >= (long long)NE * NE / 4) return;
    int m  = (int)(i4 / (NE / 4));
    int nb = (int)(i4 % (NE / 4)) * 4;
    float4 v = __ldg((const float4*)(W + (size_t)m * NE + nb));
    float wv[4] = {v.x, v.y, v.z, v.w};
    #pragma unroll
    for (int k = 0; k < 4; ++k) {
        float w = wv[k];
        if (w != 0.0f) {
            int n = nb + k;                // STP -> class B of E-output n
            int p = atomicAdd(&g_cntB[n], 1);
            if (p < CAP) {
                g_idxB[(size_t)n * CAP + p] = (unsigned short)m;
                if (p == 0) g_sclB[n] = w;
            }
        }
    }
}

// pad each list to a multiple of 64 with its sentinel index
__global__ void k_pad() {
    int n = blockIdx.x;
    int w = threadIdx.x >> 5;
    int lane = threadIdx.x & 31;
    if (n >= NN) return;
    if (w == 0) {
        unsigned short sent = (n < NE) ? (unsigned short)NI : (unsigned short)NE;
        int c = min(g_cntA[n], CAP);
        int cp = (c + 63) & ~63;
        for (int k = c + lane; k < cp; k += 32) g_idxA[(size_t)n * CAP + k] = sent;
    } else if (w == 1) {
        unsigned short sent = (n < NE) ? (unsigned short)NE : (unsigned short)NI;
        int c = min(g_cntB[n], CAP);
        int cp = (c + 63) & ~63;
        for (int k = c + lane; k < cp; k += 32) g_idxB[(size_t)n * CAP + k] = sent;
    }
}

// ---------------- state init ----------------
__global__ void k_init(const float* __restrict__ ff, const float* __restrict__ rec) {
    int gid = blockIdx.x * blockDim.x + threadIdx.x;
    if (gid < 16) {
        g_rE16[0][NE * BB + gid] = __float2half_rn(0.0f);
        g_rE16[1][NE * BB + gid] = __float2half_rn(0.0f);
        g_rI16[0][NI * BB + gid] = __float2half_rn(0.0f);
        g_rI16[1][NI * BB + gid] = __float2half_rn(0.0f);
        g_aux16[0][NE * BB + gid] = __float2half_rn(0.0f);
        g_aux16[1][NE * BB + gid] = __float2half_rn(0.0f);
    }
    if (gid >= NN * BB) return;
    int n = gid >> 4;
    int b = gid & 15;
    float r0 = rec[(size_t)b * NN + n];
    float r1 = rec[(size_t)(BB + b) * NN + n];
    g_rec0[gid] = r0;
    g_rec1[gid] = r1;
    float f = ff[((size_t)b * TT + 0) * NN + n];
    float v = f + r0 - 1.0f;
    v = v > 0.0f ? v : 0.0f;
    g_ratesf[gid] = v;
    if (n < NE) {
        g_rE16[0][gid] = __float2half_rn(v);
        float u = 0.03f, x = 1.0f;
        u = u + 0.01f * (0.03f - u) + 0.03f * (1.0f - u) * v * 0.01f;
        x = x + 0.04f * (1.0f - x) - u * x * v * 0.01f;
        g_u[gid] = u;
        g_x[gid] = x;
        g_aux16[0][gid] = __float2half_rn(u * x * v);
    } else {
        g_rI16[0][(n - NE) * BB + b] = __float2half_rn(v);
    }
}

// -------- gather-sum: 16 nnz per warp LDG.128, fp16 chunk accumulate --------
__device__ __forceinline__ void gather_class(
    const unsigned short* __restrict__ idx, int cpad,
    const char* __restrict__ rbase, int q, int h16,
    float2& f0, float2& f1, float2& f2, float2& f3)
{
    for (int it = 0; it < cpad; it += 64) {
        __half2 a0 = __float2half2_rn(0.0f);
        __half2 a1 = a0, a2 = a0, a3 = a0;
        #pragma unroll
        for (int s = 0; s < 4; ++s) {
            int m = (int)__ldg(&idx[it + s * 16 + q]);
            uint4 v = __ldg((const uint4*)(rbase + (size_t)m * 32 + h16));
            a0 = __hadd2(a0, *reinterpret_cast<__half2*>(&v.x));
            a1 = __hadd2(a1, *reinterpret_cast<__half2*>(&v.y));
            a2 = __hadd2(a2, *reinterpret_cast<__half2*>(&v.z));
            a3 = __hadd2(a3, *reinterpret_cast<__half2*>(&v.w));
        }
        float2 t;
        t = __half22float2(a0); f0.x += t.x; f0.y += t.y;
        t = __half22float2(a1); f1.x += t.x; f1.y += t.y;
        t = __half22float2(a2); f2.x += t.x; f2.y += t.y;
        t = __half22float2(a3); f3.x += t.x; f3.y += t.y;
    }
}

__device__ __forceinline__ void bfly_reduce(float2& v) {
    #pragma unroll
    for (int o = 2; o < 32; o <<= 1) {
        v.x += __shfl_xor_sync(0xffffffffu, v.x, o);
        v.y += __shfl_xor_sync(0xffffffffu, v.y, o);
    }
}

// ---------------- persistent kernel: all 100 steps, grid-wide barrier ----------------
__global__ void __launch_bounds__(BLOCK, 2) k_run(const float* __restrict__ ff,
                                                  float* __restrict__ out,
                                                  int nblocks) {
    const int lane = threadIdx.x & 31;
    const int q    = lane >> 1;
    const int h    = lane & 1;
    const int h16  = h * 16;

    for (int t = 0; t < TT; ++t) {
        const int par = t & 1;
        const char* __restrict__ rE = (const char*)&g_rE16[par][0];
        const char* __restrict__ rI = (const char*)&g_rI16[par][0];
        const char* __restrict__ aS = (const char*)&g_aux16[par][0];
        __half* __restrict__ rEn = &g_rE16[par ^ 1][0];
        __half* __restrict__ rIn = &g_rI16[par ^ 1][0];
        __half* __restrict__ aSn = &g_aux16[par ^ 1][0];

        // ---- work-steal neurons ----
        for (;;) {
            int n = 0;
            if (lane == 0) n = atomicAdd(&g_ctr[t], 1);
            n = __shfl_sync(0xffffffffu, n, 0);
            if (n >= NN) break;

            const bool isE = (n < NE);
            const char* bA = isE ? rI : rE;
            const char* bB = isE ? aS : rI;

            float2 z = make_float2(0.0f, 0.0f);
            float2 fA0 = z, fA1 = z, fA2 = z, fA3 = z;
            float2 fB0 = z, fB1 = z, fB2 = z, fB3 = z;

            {
                int cp = (min(g_cntA[n], CAP) + 63) & ~63;
                gather_class(&g_idxA[(size_t)n * CAP], cp, bA, q, h16, fA0, fA1, fA2, fA3);
            }
            {
                int cp = (min(g_cntB[n], CAP) + 63) & ~63;
                gather_class(&g_idxB[(size_t)n * CAP], cp, bB, q, h16, fB0, fB1, fB2, fB3);
            }

            bfly_reduce(fA0); bfly_reduce(fA1); bfly_reduce(fA2); bfly_reduce(fA3);
            bfly_reduce(fB0); bfly_reduce(fB1); bfly_reduce(fB2); bfly_reduce(fB3);

            if (lane < 2) {
                float sclA = g_sclA[n];
                float sclB = g_sclB[n];
                float2 fA[4] = {fA0, fA1, fA2, fA3};
                float2 fB[4] = {fB0, fB1, fB2, fB3};

                #pragma unroll
                for (int i = 0; i < 4; ++i) {
                    int b0 = h * 8 + 2 * i;
                    int e  = n * BB + b0;

                    float sAx = sclA * fA[i].x, sAy = sclA * fA[i].y;
                    float sBx = sclB * fB[i].x, sBy = sclB * fB[i].y;

                    float hidx = sAx + sBx;
                    float hidy = sAy + sBy;
                    float hid2x = isE ? sBx : sAx;   // STP part : E part
                    float hid2y = isE ? sBy : sAy;

                    float2 r0v = *reinterpret_cast<float2*>(&g_rec0[e]);
                    float2 r1v = *reinterpret_cast<float2*>(&g_rec1[e]);
                    r0v.x = r0v.x * EXP_SYN_F  + hidx * DT_SYN_F;
                    r0v.y = r0v.y * EXP_SYN_F  + hidy * DT_SYN_F;
                    r1v.x = r1v.x * EXP_NMDA_F + R_NMDA_F * hid2x * DT_NMDA_F;
                    r1v.y = r1v.y * EXP_NMDA_F + R_NMDA_F * hid2y * DT_NMDA_F;
                    *reinterpret_cast<float2*>(&g_rec0[e]) = r0v;
                    *reinterpret_cast<float2*>(&g_rec1[e]) = r1v;

                    float ffx = __ldg(&ff[((size_t)b0 * TT + t) * NN + n]);
                    float ffy = __ldg(&ff[((size_t)(b0 + 1) * TT + t) * NN + n]);
                    float netx = ffx + r0v.x + r1v.x - 1.0f;
                    float nety = ffy + r0v.y + r1v.y - 1.0f;
                    netx = netx > 0.0f ? netx : 0.0f;
                    nety = nety > 0.0f ? nety : 0.0f;

                    float2 rv = *reinterpret_cast<float2*>(&g_ratesf[e]);
                    rv.x = rv.x * EXP_TAU_F + netx * DT_TAU_F;
                    rv.y = rv.y * EXP_TAU_F + nety * DT_TAU_F;
                    *reinterpret_cast<float2*>(&g_ratesf[e]) = rv;

                    out[((size_t)b0 * TT + t) * NN + n]       = rv.x;
                    out[((size_t)(b0 + 1) * TT + t) * NN + n] = rv.y;

                    __half2 rh = __floats2half2_rn(rv.x, rv.y);
                    if (isE) {
                        *reinterpret_cast<__half2*>(&rEn[e]) = rh;
                        float2 uv = *reinterpret_cast<float2*>(&g_u[e]);
                        float2 xv = *reinterpret_cast<float2*>(&g_x[e]);
                        uv.x = uv.x + 0.01f * (0.03f - uv.x) + 0.03f * (1.0f - uv.x) * rv.x * 0.01f;
                        uv.y = uv.y + 0.01f * (0.03f - uv.y) + 0.03f * (1.0f - uv.y) * rv.y * 0.01f;
                        xv.x = xv.x + 0.04f * (1.0f - xv.x) - uv.x * xv.x * rv.x * 0.01f;
                        xv.y = xv.y + 0.04f * (1.0f - xv.y) - uv.y * xv.y * rv.y * 0.01f;
                        *reinterpret_cast<float2*>(&g_u[e]) = uv;
                        *reinterpret_cast<float2*>(&g_x[e]) = xv;
                        *reinterpret_cast<__half2*>(&aSn[e]) =
                            __floats2half2_rn(uv.x * xv.x * rv.x, uv.y * xv.y * rv.y);
                    } else {
                        *reinterpret_cast<__half2*>(&rIn[(n - NE) * BB + b0]) = rh;
                    }
                }
            }
        }

        // ---- grid-wide barrier (sense via monotonic phase) ----
        __syncthreads();
        __threadfence();            // gpu-scope: orders writes AND invalidates L1D (CCTL.IVALL)
        if (threadIdx.x == 0) {
            int arrived = atomicAdd(&g_bar, 1) + 1;
            if (arrived == nblocks * (t + 1)) {
                g_sense = t + 1;    // release
            } else {
                while (g_sense < t + 1) { }   // volatile spin (bypasses L1)
            }
        }
        __syncthreads();
    }
}

// ---------------- launcher ----------------
extern "C" void kernel_launch(void* const* d_in, const int* in_sizes, int n_in,
                              void* d_out, int out_size) {
    const float* ff   = nullptr;
    const float* rec  = nullptr;
    const float* wab  = nullptr;
    const float* wstp = nullptr;
    for (int i = 0; i < n_in; ++i) {
        switch (in_sizes[i]) {
            case 16384000:  ff   = (const float*)d_in[i]; break;
            case 327680:    rec  = (const float*)d_in[i]; break;
            case 104857600: wab  = (const float*)d_in[i]; break;
            case 67108864:  wstp = (const float*)d_in[i]; break;
            default: break;
        }
    }
    if (!ff || !rec || !wab || !wstp) {
        ff   = (const float*)d_in[0];
        rec  = (const float*)d_in[1];
        wab  = (const float*)d_in[2];
        wstp = (const float*)d_in[3];
    }
    float* out = (float*)d_out;

    k_zero<<<(NN + 255) / 256, 256>>>();
    {
        long long tot = (long long)NN * NN / 4;
        k_fill_wab<<<(unsigned)((tot + 255) / 256), 256>>>(wab);
    }
    {
        long long tot = (long long)NE * NE / 4;
        k_fill_wstp<<<(unsigned)((tot + 255) / 256), 256>>>(wstp);
    }
    k_pad<<<NN, 64>>>();
    k_init<<<(NN * BB + 255) / 256, 256>>>(ff, rec);

    // persistent kernel: grid sized to guaranteed co-residency
    int dev = 0;
    cudaGetDevice(&dev);
    int sms = 0;
    cudaDeviceGetAttribute(&sms, cudaDevAttrMultiProcessorCount, dev);
    if (sms <= 0) sms = 148;
    int occ = 0;
    cudaOccupancyMaxActiveBlocksPerMultiprocessor(&occ, k_run, BLOCK, 0);
    if (occ < 1) occ = 1;
    int grid = sms * occ;
    k_run<<<grid, BLOCK>>>(ff, out, grid);
}